// round 16
// baseline (speedup 1.0000x reference)
#include <cuda_runtime.h>
#include <cuda_fp16.h>
#include <cstdint>
#include <math.h>

#define DIMN 768
#define HIDN 1536
#define NB 8
#define NS 2048
#define NTOK (NB*NS)
#define QKVN 2304

#define INV_SCALE_F 0.03608439182435161f   // 1/sqrt(768)
#define QSCALE 32.0f                       // int8 quant scale for Q,K
#define ALPHA_SCALE (INV_SCALE_F / (QSCALE * QSCALE))

static __device__ __forceinline__ float geluf(float x) {
    return 0.5f * x * (1.0f + erff(x * 0.70710678118654752f));
}

// ---------------- scratch (static device globals; allocation-free) ----------
__device__ __half g_xh[(long)NTOK * DIMN];
__device__ signed char g_QKi8[(long)2 * NTOK * DIMN];  // [Q][K] int8, dense
__device__ __half g_Vh[(long)NTOK * DIMN];
__device__ __half g_alphah[(long)NB * NS * NS];
__device__ __half g_attnh[(long)NTOK * DIMN];
__device__ float  g_t1[(long)NTOK * DIMN];
__device__ float  g_h32[(long)NTOK * DIMN];
__device__ __half g_hh[(long)NTOK * DIMN];
__device__ __half g_mlph[(long)NTOK * HIDN];
__device__ float  g_t2[(long)NTOK * DIMN];
__device__ __half g_Wqkvh[QKVN * DIMN];            // rows: Wq|Wk|Wv
__device__ float  g_bqkv[QKVN];
__device__ __half g_Wph[DIMN * DIMN];
__device__ __half g_W1h[HIDN * DIMN];
__device__ __half g_W2h[DIMN * HIDN];

// ---------------- small PTX helpers -----------------------------------------
__device__ __forceinline__ uint32_t smem_u32(const void* p) {
    uint32_t a;
    asm("{ .reg .u64 t; cvta.to.shared.u64 t, %1; cvt.u32.u64 %0, t; }" : "=r"(a) : "l"(p));
    return a;
}
__device__ __forceinline__ void cpa16(uint32_t dst, const void* src) {
    asm volatile("cp.async.cg.shared.global [%0], [%1], 16;" :: "r"(dst), "l"(src));
}
__device__ __forceinline__ void cp_commit() { asm volatile("cp.async.commit_group;"); }
template<int N> __device__ __forceinline__ void cp_wait() {
    asm volatile("cp.async.wait_group %0;" :: "n"(N));
}
__device__ __forceinline__ void ldm_x4(uint32_t& r0, uint32_t& r1, uint32_t& r2, uint32_t& r3,
                                       uint32_t addr) {
    asm volatile("ldmatrix.sync.aligned.m8n8.x4.shared.b16 {%0,%1,%2,%3}, [%4];"
                 : "=r"(r0), "=r"(r1), "=r"(r2), "=r"(r3) : "r"(addr));
}
__device__ __forceinline__ void ldm_x4_t(uint32_t& r0, uint32_t& r1, uint32_t& r2, uint32_t& r3,
                                         uint32_t addr) {
    asm volatile("ldmatrix.sync.aligned.m8n8.x4.trans.shared.b16 {%0,%1,%2,%3}, [%4];"
                 : "=r"(r0), "=r"(r1), "=r"(r2), "=r"(r3) : "r"(addr));
}
__device__ __forceinline__ void mma_f16(float* c, const uint32_t* a, const uint32_t* b) {
    asm volatile(
        "mma.sync.aligned.m16n8k16.row.col.f32.f16.f16.f32 "
        "{%0,%1,%2,%3}, {%4,%5,%6,%7}, {%8,%9}, {%0,%1,%2,%3};"
        : "+f"(c[0]), "+f"(c[1]), "+f"(c[2]), "+f"(c[3])
        : "r"(a[0]), "r"(a[1]), "r"(a[2]), "r"(a[3]), "r"(b[0]), "r"(b[1]));
}
__device__ __forceinline__ void mma_i8(int* c, const uint32_t* a, const uint32_t* b) {
    asm volatile(
        "mma.sync.aligned.m16n8k32.row.col.s32.s8.s8.s32 "
        "{%0,%1,%2,%3}, {%4,%5,%6,%7}, {%8,%9}, {%0,%1,%2,%3};"
        : "+r"(c[0]), "+r"(c[1]), "+r"(c[2]), "+r"(c[3])
        : "r"(a[0]), "r"(a[1]), "r"(a[2]), "r"(a[3]), "r"(b[0]), "r"(b[1]));
}

// ---------------- fp16 GEMM (proven R15 core) --------------------------------
enum { EPI_NONE = 0, EPI_SCALE = 1, EPI_BIAS = 2, EPI_BIAS_RESID = 3, EPI_BIAS_GELU = 4 };

#define NTHREADS 256
#define BK 128
#define A_BYTES (128 * BK * 2)     // 32768  (row = 256B = 16 chunks)
#define B_BYTES (256 * BK * 2)     // 65536
#define STAGE_BYTES (A_BYTES + B_BYTES)          // 98304
#define SMEM_GEMM (2 * STAGE_BYTES)              // 196608

template<bool BT>
__device__ __forceinline__ void load_tiles(const __half* __restrict__ A, int lda,
                                           const __half* __restrict__ Bg, int ldb,
                                           int m0, int n0, int kb,
                                           uint32_t as, uint32_t bs, int tid) {
    {
        const __half* src = A + (long)m0 * lda + kb * BK;
        #pragma unroll
        for (int i = 0; i < 8; i++) {
            int idx = tid + i * NTHREADS;
            int r = idx >> 4, c = idx & 15;
            cpa16(as + r * 256 + ((c ^ (r & 7)) << 4), src + (long)r * lda + c * 8);
        }
    }
    if (BT) {
        const __half* src = Bg + (long)n0 * ldb + kb * BK;
        #pragma unroll
        for (int i = 0; i < 16; i++) {
            int idx = tid + i * NTHREADS;
            int r = idx >> 4, c = idx & 15;
            cpa16(bs + r * 256 + ((c ^ (r & 7)) << 4), src + (long)r * ldb + c * 8);
        }
    } else {
        const __half* src = Bg + (long)(kb * BK) * ldb + n0;
        #pragma unroll
        for (int i = 0; i < 16; i++) {
            int idx = tid + i * NTHREADS;
            int r = idx >> 5, c = idx & 31;
            cpa16(bs + r * 512 + ((c ^ (r & 7)) << 4), src + (long)r * ldb + c * 8);
        }
    }
}

template<bool BT>
__device__ __forceinline__ void frag_load(uint32_t Ab, uint32_t Bb, int kk,
                                          int a_m, int a_kc,
                                          int b_n, int b_kc, int bn_k, int bn_nc,
                                          uint32_t af[4][4], uint32_t bf[8][2]) {
    #pragma unroll
    for (int mi = 0; mi < 4; mi++) {
        const int m = a_m + mi * 16;
        const int kc = kk * 2 + a_kc;
        ldm_x4(af[mi][0], af[mi][1], af[mi][2], af[mi][3],
               Ab + m * 256 + ((kc ^ (m & 7)) << 4));
    }
    #pragma unroll
    for (int p = 0; p < 4; p++) {
        uint32_t r0, r1, r2, r3;
        if (BT) {
            const int n = b_n + p * 16;
            const int kc = kk * 2 + b_kc;
            ldm_x4(r0, r1, r2, r3, Bb + n * 256 + ((kc ^ (n & 7)) << 4));
        } else {
            const int kr = kk * 16 + bn_k;
            const int nc = bn_nc + 2 * p;
            ldm_x4_t(r0, r1, r2, r3, Bb + kr * 512 + ((nc ^ (kr & 7)) << 4));
        }
        bf[2 * p][0] = r0; bf[2 * p][1] = r1;
        bf[2 * p + 1][0] = r2; bf[2 * p + 1][1] = r3;
    }
}

template<int EPI, bool BT, bool OUT16, bool SPLITC>
__global__ __launch_bounds__(NTHREADS, 1)
void gemm_h(const __half* __restrict__ A, int lda, long sA,
            const __half* __restrict__ Bg, int ldb, long sB,
            void* __restrict__ Cv, int ldc, long sC,
            signed char* __restrict__ i8dst,
            const float* __restrict__ bias,
            const float* __restrict__ resid,
            int Kdim) {
    extern __shared__ __align__(1024) char smem[];
    const uint32_t sb = smem_u32(smem);
    const int tid = threadIdx.x;
    const long bz = blockIdx.z;
    A += bz * sA; Bg += bz * sB;

    const int m0 = blockIdx.y * 128;
    const int n0 = blockIdx.x * 256;

    const int lane = tid & 31;
    const int g = lane >> 2, tg = lane & 3;
    const int wid = tid >> 5;
    const int wm0 = (wid & 1) * 64;
    const int wn0 = (wid >> 1) * 64;

    const int a_m = wm0 + (lane & 15);
    const int a_kc = lane >> 4;
    const int b_n = wn0 + (lane & 7) + ((lane >> 4) << 3);
    const int b_kc = (lane >> 3) & 1;
    const int bn_k = (lane & 7) + (lane & 8);
    const int bn_nc = (wn0 >> 3) + (lane >> 4);

    float acc[4][8][4];
    #pragma unroll
    for (int i = 0; i < 4; i++)
        #pragma unroll
        for (int j = 0; j < 8; j++)
            #pragma unroll
            for (int r = 0; r < 4; r++) acc[i][j][r] = 0.0f;

    const int nk = Kdim / BK;
    load_tiles<BT>(A, lda, Bg, ldb, m0, n0, 0, sb, sb + A_BYTES, tid);
    cp_commit();
    load_tiles<BT>(A, lda, Bg, ldb, m0, n0, 1, sb + STAGE_BYTES, sb + STAGE_BYTES + A_BYTES, tid);
    cp_commit();

    for (int kb = 0; kb < nk; ++kb) {
        if (kb + 1 < nk) cp_wait<1>(); else cp_wait<0>();
        __syncthreads();

        const uint32_t Ab = sb + (kb & 1) * STAGE_BYTES;
        const uint32_t Bb = Ab + A_BYTES;

        uint32_t af[2][4][4];
        uint32_t bf[2][8][2];
        frag_load<BT>(Ab, Bb, 0, a_m, a_kc, b_n, b_kc, bn_k, bn_nc, af[0], bf[0]);

        #pragma unroll
        for (int kk = 0; kk < 8; kk++) {
            const int cur = kk & 1;
            if (kk < 7)
                frag_load<BT>(Ab, Bb, kk + 1, a_m, a_kc, b_n, b_kc, bn_k, bn_nc,
                              af[cur ^ 1], bf[cur ^ 1]);
            #pragma unroll
            for (int mi = 0; mi < 4; mi++)
                #pragma unroll
                for (int nj = 0; nj < 8; nj++)
                    mma_f16(acc[mi][nj], af[cur][mi], bf[cur][nj]);
        }
        __syncthreads();

        if (kb + 2 < nk) {
            const uint32_t st = sb + (kb & 1) * STAGE_BYTES;
            load_tiles<BT>(A, lda, Bg, ldb, m0, n0, kb + 2, st, st + A_BYTES, tid);
            cp_commit();
        }
    }

    // epilogue
    const int seg = SPLITC ? (n0 / DIMN) : 0;
    #pragma unroll
    for (int mi = 0; mi < 4; mi++) {
        #pragma unroll
        for (int r2 = 0; r2 < 2; r2++) {
            const int row = m0 + wm0 + mi * 16 + g + r2 * 8;
            #pragma unroll
            for (int nj = 0; nj < 8; nj++) {
                const int col = n0 + wn0 + nj * 8 + 2 * tg;
                float v0 = acc[mi][nj][r2 * 2 + 0];
                float v1 = acc[mi][nj][r2 * 2 + 1];
                if (EPI == EPI_SCALE) { v0 *= INV_SCALE_F; v1 *= INV_SCALE_F; }
                if (EPI == EPI_BIAS || EPI == EPI_BIAS_RESID || EPI == EPI_BIAS_GELU) {
                    v0 += bias[col]; v1 += bias[col + 1];
                }
                if (SPLITC) {
                    const int lc = col - seg * DIMN;
                    const long base = (long)row * DIMN + lc;
                    if (seg < 2) {
                        // quantize Q/K to int8 (scale 32)
                        int q0 = __float2int_rn(v0 * QSCALE);
                        int q1 = __float2int_rn(v1 * QSCALE);
                        q0 = max(-127, min(127, q0));
                        q1 = max(-127, min(127, q1));
                        char2 cc; cc.x = (signed char)q0; cc.y = (signed char)q1;
                        *(char2*)(i8dst + (long)seg * NTOK * DIMN + base) = cc;
                    } else {
                        *(__half2*)((__half*)Cv + base) = __floats2half2_rn(v0, v1);
                    }
                } else {
                    const long off = (long)row * ldc + col + bz * sC;
                    if (EPI == EPI_BIAS_RESID) {
                        float2 rr = *(const float2*)(resid + off);
                        v0 += rr.x; v1 += rr.y;
                    }
                    if (EPI == EPI_BIAS_GELU) { v0 = geluf(v0); v1 = geluf(v1); }
                    if (OUT16) {
                        *(__half2*)((__half*)Cv + off) = __floats2half2_rn(v0, v1);
                    } else {
                        float2 o; o.x = v0; o.y = v1;
                        *(float2*)((float*)Cv + off) = o;
                    }
                }
            }
        }
    }
}

// ---------------- int8 NT GEMM for alpha = Q @ K^T ---------------------------
// A = Qi8 [M,768], B = Ki8 [N,768] (NT). BK=128 bytes -> rows are 128B =
// 8 chunks, IDENTICAL swizzle/ldmatrix addressing to the fp16 path (the
// m16n8k32 s8 fragment byte-map matches the k16 f16 map). 4 k32 steps / BK.
// Epilogue: alpha_h2 = acc * INV_SCALE/1024.
#define A8_BYTES (128 * 128)       // 16384
#define B8_BYTES (256 * 128)       // 32768
#define STAGE8 (A8_BYTES + B8_BYTES)             // 49152
#define SMEM_GEMM8 (2 * STAGE8)                  // 98304

__device__ __forceinline__ void load_tiles8(const signed char* __restrict__ A,
                                            const signed char* __restrict__ Bg,
                                            int m0, int n0, int kb,
                                            uint32_t as, uint32_t bs, int tid) {
    {
        const signed char* src = A + (long)m0 * DIMN + kb * 128;
        #pragma unroll
        for (int i = 0; i < 4; i++) {
            int idx = tid + i * NTHREADS;
            int r = idx >> 3, c = idx & 7;
            cpa16(as + r * 128 + ((c ^ (r & 7)) << 4), src + (long)r * DIMN + c * 16);
        }
    }
    {
        const signed char* src = Bg + (long)n0 * DIMN + kb * 128;
        #pragma unroll
        for (int i = 0; i < 8; i++) {
            int idx = tid + i * NTHREADS;
            int r = idx >> 3, c = idx & 7;
            cpa16(bs + r * 128 + ((c ^ (r & 7)) << 4), src + (long)r * DIMN + c * 16);
        }
    }
}

__device__ __forceinline__ void frag_load8(uint32_t Ab, uint32_t Bb, int kk,
                                           int a_m, int a_kc,
                                           int b_n, int b_kc,
                                           uint32_t af[4][4], uint32_t bf[8][2]) {
    #pragma unroll
    for (int mi = 0; mi < 4; mi++) {
        const int m = a_m + mi * 16;
        const int kc = kk * 2 + a_kc;
        ldm_x4(af[mi][0], af[mi][1], af[mi][2], af[mi][3],
               Ab + m * 128 + ((kc ^ (m & 7)) << 4));
    }
    #pragma unroll
    for (int p = 0; p < 4; p++) {
        uint32_t r0, r1, r2, r3;
        const int n = b_n + p * 16;
        const int kc = kk * 2 + b_kc;
        ldm_x4(r0, r1, r2, r3, Bb + n * 128 + ((kc ^ (n & 7)) << 4));
        bf[2 * p][0] = r0; bf[2 * p][1] = r1;
        bf[2 * p + 1][0] = r2; bf[2 * p + 1][1] = r3;
    }
}

__global__ __launch_bounds__(NTHREADS, 1)
void gemm_i8(const signed char* __restrict__ Qi, const signed char* __restrict__ Ki,
             __half* __restrict__ C) {
    extern __shared__ __align__(1024) char smem[];
    const uint32_t sb = smem_u32(smem);
    const int tid = threadIdx.x;
    const long bz = blockIdx.z;
    const signed char* A = Qi + bz * (long)NS * DIMN;
    const signed char* B = Ki + bz * (long)NS * DIMN;

    const int m0 = blockIdx.y * 128;
    const int n0 = blockIdx.x * 256;

    const int lane = tid & 31;
    const int g = lane >> 2, tg = lane & 3;
    const int wid = tid >> 5;
    const int wm0 = (wid & 1) * 64;
    const int wn0 = (wid >> 1) * 64;

    const int a_m = wm0 + (lane & 15);
    const int a_kc = lane >> 4;
    const int b_n = wn0 + (lane & 7) + ((lane >> 4) << 3);
    const int b_kc = (lane >> 3) & 1;

    int acc[4][8][4];
    #pragma unroll
    for (int i = 0; i < 4; i++)
        #pragma unroll
        for (int j = 0; j < 8; j++)
            #pragma unroll
            for (int r = 0; r < 4; r++) acc[i][j][r] = 0;

    const int nk = DIMN / 128;   // 6
    load_tiles8(A, B, m0, n0, 0, sb, sb + A8_BYTES, tid);
    cp_commit();
    load_tiles8(A, B, m0, n0, 1, sb + STAGE8, sb + STAGE8 + A8_BYTES, tid);
    cp_commit();

    for (int kb = 0; kb < nk; ++kb) {
        if (kb + 1 < nk) cp_wait<1>(); else cp_wait<0>();
        __syncthreads();

        const uint32_t Ab = sb + (kb & 1) * STAGE8;
        const uint32_t Bb = Ab + A8_BYTES;

        uint32_t af[2][4][4];
        uint32_t bf[2][8][2];
        frag_load8(Ab, Bb, 0, a_m, a_kc, b_n, b_kc, af[0], bf[0]);

        #pragma unroll
        for (int kk = 0; kk < 4; kk++) {     // 4 x k32 per BK=128
            const int cur = kk & 1;
            if (kk < 3)
                frag_load8(Ab, Bb, kk + 1, a_m, a_kc, b_n, b_kc, af[cur ^ 1], bf[cur ^ 1]);
            #pragma unroll
            for (int mi = 0; mi < 4; mi++)
                #pragma unroll
                for (int nj = 0; nj < 8; nj++)
                    mma_i8(acc[mi][nj], af[cur][mi], bf[cur][nj]);
        }
        __syncthreads();

        if (kb + 2 < nk) {
            const uint32_t st = sb + (kb & 1) * STAGE8;
            load_tiles8(A, B, m0, n0, kb + 2, st, st + A8_BYTES, tid);
            cp_commit();
        }
    }

    __half* Co = C + bz * (long)NS * NS;
    #pragma unroll
    for (int mi = 0; mi < 4; mi++) {
        #pragma unroll
        for (int r2 = 0; r2 < 2; r2++) {
            const int row = m0 + wm0 + mi * 16 + g + r2 * 8;
            #pragma unroll
            for (int nj = 0; nj < 8; nj++) {
                const int col = n0 + wn0 + nj * 8 + 2 * tg;
                float v0 = (float)acc[mi][nj][r2 * 2 + 0] * ALPHA_SCALE;
                float v1 = (float)acc[mi][nj][r2 * 2 + 1] * ALPHA_SCALE;
                *(__half2*)(Co + (long)row * NS + col) = __floats2half2_rn(v0, v1);
            }
        }
    }
}

// ---------------- fp32 -> fp16 conversion (x) --------------------------------
__global__ __launch_bounds__(256)
void cvt_kernel(const float* __restrict__ src, __half* __restrict__ dst) {
    const long i = ((long)blockIdx.x * 256 + threadIdx.x) * 4;
    float4 v = *(const float4*)(src + i);
    uint2 o;
    __half2 h0 = __floats2half2_rn(v.x, v.y);
    __half2 h1 = __floats2half2_rn(v.z, v.w);
    o.x = *(uint32_t*)&h0; o.y = *(uint32_t*)&h1;
    *(uint2*)(dst + i) = o;
}

// ---------------- weights (Wq|Wk|Wv concat, Wp, W1, W2) + bias concat --------
#define WSZ (DIMN * DIMN)
#define W1SZ (HIDN * DIMN)
#define WTOTAL (4L * WSZ + 2L * W1SZ)
#define CVT_UNITS (WTOTAL / 4 + QKVN / 4)
#define CVTW_GRID ((CVT_UNITS + 255) / 256)
__global__ __launch_bounds__(256)
void cvt_weights(const float* __restrict__ Wq, const float* __restrict__ Wk,
                 const float* __restrict__ Wv, const float* __restrict__ Wp,
                 const float* __restrict__ W1, const float* __restrict__ W2,
                 const float* __restrict__ bq, const float* __restrict__ bk,
                 const float* __restrict__ bv,
                 __half* __restrict__ dWqkv, __half* __restrict__ dWp,
                 __half* __restrict__ dW1, __half* __restrict__ dW2,
                 float* __restrict__ dbqkv) {
    const long u = (long)blockIdx.x * 256 + threadIdx.x;
    if (u >= CVT_UNITS) return;
    long i = u * 4;
    if (i < WTOTAL) {
        const float* src;
        __half* dst;
        if (i < WSZ)              { src = Wq; dst = dWqkv; }
        else if (i < 2L * WSZ)    { src = Wk; dst = dWqkv + WSZ; i -= WSZ; }
        else if (i < 3L * WSZ)    { src = Wv; dst = dWqkv + 2L * WSZ; i -= 2L * WSZ; }
        else if (i < 4L * WSZ)    { src = Wp; dst = dWp; i -= 3L * WSZ; }
        else if (i < 4L * WSZ + W1SZ) { src = W1; dst = dW1; i -= 4L * WSZ; }
        else                      { src = W2; dst = dW2; i -= 4L * WSZ + W1SZ; }
        float4 v = *(const float4*)(src + i);
        uint2 o;
        __half2 h0 = __floats2half2_rn(v.x, v.y);
        __half2 h1 = __floats2half2_rn(v.z, v.w);
        o.x = *(uint32_t*)&h0; o.y = *(uint32_t*)&h1;
        *(uint2*)(dst + i) = o;
    } else {
        long j = i - WTOTAL;
        const float* src = (j < DIMN) ? (bq + j)
                         : (j < 2 * DIMN) ? (bk + (j - DIMN))
                                          : (bv + (j - 2 * DIMN));
        *(float4*)(dbqkv + j) = *(const float4*)src;
    }
}

// ---------------- softmax over rows of 2048: fp16 in-place, single pass ------
__global__ __launch_bounds__(256)
void softmax_h(__half* __restrict__ a) {
    __shared__ float red[8];
    __shared__ float bc;
    const int t = threadIdx.x;
    const int lane = t & 31, wid = t >> 5;
    __half* p = a + (long)blockIdx.x * 2048;

    uint4 w = reinterpret_cast<uint4*>(p)[t];
    float e[8];
    {
        float2 a0 = __half22float2(*(__half2*)&w.x);
        float2 a1 = __half22float2(*(__half2*)&w.y);
        float2 a2 = __half22float2(*(__half2*)&w.z);
        float2 a3 = __half22float2(*(__half2*)&w.w);
        e[0] = __expf(a0.x); e[1] = __expf(a0.y);
        e[2] = __expf(a1.x); e[3] = __expf(a1.y);
        e[4] = __expf(a2.x); e[5] = __expf(a2.y);
        e[6] = __expf(a3.x); e[7] = __expf(a3.y);
    }

    float s = (e[0] + e[1]) + (e[2] + e[3]) + (e[4] + e[5]) + (e[6] + e[7]);
    #pragma unroll
    for (int o = 16; o > 0; o >>= 1) s += __shfl_xor_sync(0xffffffffu, s, o);
    if (lane == 0) red[wid] = s;
    __syncthreads();
    if (t == 0) {
        float ss = 0.0f;
        #pragma unroll
        for (int i = 0; i < 8; i++) ss += red[i];
        bc = 1.0f / ss;
    }
    __syncthreads();
    const float inv = bc;

    __half2 h0 = __floats2half2_rn(e[0] * inv, e[1] * inv);
    __half2 h1 = __floats2half2_rn(e[2] * inv, e[3] * inv);
    __half2 h2 = __floats2half2_rn(e[4] * inv, e[5] * inv);
    __half2 h3 = __floats2half2_rn(e[6] * inv, e[7] * inv);
    uint4 o;
    o.x = *(uint32_t*)&h0; o.y = *(uint32_t*)&h1;
    o.z = *(uint32_t*)&h2; o.w = *(uint32_t*)&h3;
    reinterpret_cast<uint4*>(p)[t] = o;
}

// ---------------- LayerNorm over rows of 768 (one warp per row) --------------
__global__ __launch_bounds__(128)
void ln_kernel(const float* __restrict__ in, const float* __restrict__ gamma,
               const float* __restrict__ beta, float* __restrict__ out,
               __half* __restrict__ out16) {
    const int wid = threadIdx.x >> 5, lane = threadIdx.x & 31;
    const long row = (long)blockIdx.x * 4 + wid;
    const float4* p = (const float4*)(in + row * DIMN);

    float4 v[6];
    float s = 0.0f, sq = 0.0f;
    #pragma unroll
    for (int j = 0; j < 6; j++) {
        v[j] = p[lane + 32 * j];
        s  += (v[j].x + v[j].y) + (v[j].z + v[j].w);
        sq += (v[j].x * v[j].x + v[j].y * v[j].y) + (v[j].z * v[j].z + v[j].w * v[j].w);
    }
    #pragma unroll
    for (int o = 16; o > 0; o >>= 1) {
        s  += __shfl_xor_sync(0xffffffffu, s, o);
        sq += __shfl_xor_sync(0xffffffffu, sq, o);
    }
    const float mean = s * (1.0f / DIMN);
    const float var  = sq * (1.0f / DIMN) - mean * mean;
    const float ri   = rsqrtf(var + 1e-12f);

    const float4* gp = (const float4*)gamma;
    const float4* bp = (const float4*)beta;
    float4* o = (float4*)(out + row * DIMN);
    #pragma unroll
    for (int j = 0; j < 6; j++) {
        float4 g4 = gp[lane + 32 * j], b4 = bp[lane + 32 * j], r;
        r.x = (v[j].x - mean) * ri * g4.x + b4.x;
        r.y = (v[j].y - mean) * ri * g4.y + b4.y;
        r.z = (v[j].z - mean) * ri * g4.z + b4.z;
        r.w = (v[j].w - mean) * ri * g4.w + b4.w;
        o[lane + 32 * j] = r;
        if (out16) {
            __half2 h0 = __floats2half2_rn(r.x, r.y);
            __half2 h1 = __floats2half2_rn(r.z, r.w);
            uint2 w; w.x = *(uint32_t*)&h0; w.y = *(uint32_t*)&h1;
            *(uint2*)(out16 + row * DIMN + (lane + 32 * j) * 4) = w;
        }
    }
}

// ---------------- launch ------------------------------------------------------
extern "C" void kernel_launch(void* const* d_in, const int* in_sizes, int n_in,
                              void* d_out, int out_size) {
    const float* x   = (const float*)d_in[0];
    const float* Wq  = (const float*)d_in[1];
    const float* bq  = (const float*)d_in[2];
    const float* Wk  = (const float*)d_in[3];
    const float* bk  = (const float*)d_in[4];
    const float* Wv  = (const float*)d_in[5];
    const float* bv  = (const float*)d_in[6];
    const float* Wp  = (const float*)d_in[7];
    const float* bp  = (const float*)d_in[8];
    const float* g1  = (const float*)d_in[9];
    const float* be1 = (const float*)d_in[10];
    const float* W1  = (const float*)d_in[11];
    const float* b1  = (const float*)d_in[12];
    const float* W2  = (const float*)d_in[13];
    const float* b2  = (const float*)d_in[14];
    const float* g2  = (const float*)d_in[15];
    const float* be2 = (const float*)d_in[16];
    float* out = (float*)d_out;

    __half *xh, *Vh, *alphah, *attnh, *hh, *mlph;
    __half *Wqkvh, *Wph, *W1h, *W2h;
    signed char* QKi8;
    float *t1, *h32, *t2, *bqkv;
    cudaGetSymbolAddress((void**)&xh, g_xh);
    cudaGetSymbolAddress((void**)&QKi8, g_QKi8);
    cudaGetSymbolAddress((void**)&Vh, g_Vh);
    cudaGetSymbolAddress((void**)&alphah, g_alphah);
    cudaGetSymbolAddress((void**)&attnh, g_attnh);
    cudaGetSymbolAddress((void**)&t1, g_t1);
    cudaGetSymbolAddress((void**)&h32, g_h32);
    cudaGetSymbolAddress((void**)&hh, g_hh);
    cudaGetSymbolAddress((void**)&mlph, g_mlph);
    cudaGetSymbolAddress((void**)&t2, g_t2);
    cudaGetSymbolAddress((void**)&Wqkvh, g_Wqkvh);
    cudaGetSymbolAddress((void**)&bqkv, g_bqkv);
    cudaGetSymbolAddress((void**)&Wph, g_Wph);
    cudaGetSymbolAddress((void**)&W1h, g_W1h);
    cudaGetSymbolAddress((void**)&W2h, g_W2h);

    signed char* Qi8 = QKi8;
    signed char* Ki8 = QKi8 + (long)NTOK * DIMN;

    cudaFuncSetAttribute(gemm_h<EPI_BIAS, true, true, true>,          cudaFuncAttributeMaxDynamicSharedMemorySize, SMEM_GEMM);
    cudaFuncSetAttribute(gemm_i8,                                     cudaFuncAttributeMaxDynamicSharedMemorySize, SMEM_GEMM8);
    cudaFuncSetAttribute(gemm_h<EPI_NONE, false, true, false>,        cudaFuncAttributeMaxDynamicSharedMemorySize, SMEM_GEMM);
    cudaFuncSetAttribute(gemm_h<EPI_BIAS_RESID, true, false, false>,  cudaFuncAttributeMaxDynamicSharedMemorySize, SMEM_GEMM);
    cudaFuncSetAttribute(gemm_h<EPI_BIAS_GELU, true, true, false>,    cudaFuncAttributeMaxDynamicSharedMemorySize, SMEM_GEMM);

    // #1: x fp32->fp16 ; #2: weights (QKV concat) + bias concat
    cvt_kernel<<<(long)NTOK * DIMN / 1024, 256>>>(x, xh);
    cvt_weights<<<CVTW_GRID, 256>>>(Wq, Wk, Wv, Wp, W1, W2, bq, bk, bv,
                                    Wqkvh, Wph, W1h, W2h, bqkv);

    const dim3 blk(NTHREADS);
    const long sQK = (long)NS * DIMN;
    const long sAl = (long)NS * NS;

    // #3: fused QKV projection — Q,K quantized to int8, V fp16 (SPLITC)
    gemm_h<EPI_BIAS, true, true, true><<<dim3(9, 128, 1), blk, SMEM_GEMM>>>(
        xh, DIMN, 0, Wqkvh, DIMN, 0, Vh, DIMN, 0, QKi8, bqkv, nullptr, DIMN);

    // #4: alpha = Q @ K^T / sqrt(D)  — INT8 IMMA (batched)
    gemm_i8<<<dim3(8, 16, NB), blk, SMEM_GEMM8>>>(Qi8, Ki8, alphah);

    // #5: softmax rows (fp16 in-place, single pass)
    softmax_h<<<NTOK, 256>>>(alphah);

    // #6 (ncu capture): attn = alpha @ V (batched NN, fp16)
    gemm_h<EPI_NONE, false, true, false><<<dim3(3, 16, NB), blk, SMEM_GEMM>>>(
        alphah, NS, sAl, Vh, DIMN, sQK, attnh, DIMN, sQK, nullptr, nullptr, nullptr, NS);

    // proj + residual: t1 = attn @ Wp^T + bp + x  (fp32 out)
    gemm_h<EPI_BIAS_RESID, true, false, false><<<dim3(3, 128, 1), blk, SMEM_GEMM>>>(
        attnh, DIMN, 0, Wph, DIMN, 0, t1, DIMN, 0, nullptr, bp, x, DIMN);

    // h = LN(t1)  (fp32 + fp16)
    ln_kernel<<<NTOK / 4, 128>>>(t1, g1, be1, h32, hh);

    // mlp = gelu(h @ W1^T + b1)  (fp16 out)
    gemm_h<EPI_BIAS_GELU, true, true, false><<<dim3(6, 128, 1), blk, SMEM_GEMM>>>(
        hh, DIMN, 0, W1h, DIMN, 0, mlph, HIDN, 0, nullptr, b1, nullptr, DIMN);

    // t2 = mlp @ W2^T + b2 + h  (fp32 out)
    gemm_h<EPI_BIAS_RESID, true, false, false><<<dim3(3, 128, 1), blk, SMEM_GEMM>>>(
        mlph, HIDN, 0, W2h, HIDN, 0, t2, DIMN, 0, nullptr, b2, h32, HIDN);

    // out = LN(t2)
    ln_kernel<<<NTOK / 4, 128>>>(t2, g2, be2, out, nullptr);
}

// round 17
// speedup vs baseline: 1.3024x; 1.3024x over previous
#include <cuda_runtime.h>
#include <cuda_fp16.h>
#include <cstdint>
#include <math.h>

#define DIMN 768
#define HIDN 1536
#define NB 8
#define NS 2048
#define NTOK (NB*NS)
#define QKVN 2304

#define INV_SCALE_F 0.03608439182435161f   // 1/sqrt(768)

static __device__ __forceinline__ float geluf(float x) {
    return 0.5f * x * (1.0f + erff(x * 0.70710678118654752f));
}

// ---------------- scratch (static device globals; allocation-free) ----------
__device__ __half g_xh[(long)NTOK * DIMN];
__device__ __half g_QKV3[(long)3 * NTOK * DIMN];   // [Q][K][V], each dense [NTOK x DIMN]
__device__ __half g_alphah[(long)NB * NS * NS];    // exp(logits), unnormalized
__device__ float  g_rowsum[NTOK];                  // per-row sum of exp
__device__ __half g_attnh[(long)NTOK * DIMN];
__device__ float  g_t1[(long)NTOK * DIMN];
__device__ float  g_h32[(long)NTOK * DIMN];
__device__ __half g_hh[(long)NTOK * DIMN];
__device__ __half g_mlph[(long)NTOK * HIDN];
__device__ float  g_t2[(long)NTOK * DIMN];
__device__ __half g_Wqkvh[QKVN * DIMN];            // rows: Wq|Wk|Wv
__device__ float  g_bqkv[QKVN];
__device__ __half g_Wph[DIMN * DIMN];
__device__ __half g_W1h[HIDN * DIMN];
__device__ __half g_W2h[DIMN * HIDN];

// ---------------- small PTX helpers -----------------------------------------
__device__ __forceinline__ uint32_t smem_u32(const void* p) {
    uint32_t a;
    asm("{ .reg .u64 t; cvta.to.shared.u64 t, %1; cvt.u32.u64 %0, t; }" : "=r"(a) : "l"(p));
    return a;
}
__device__ __forceinline__ void cpa16(uint32_t dst, const __half* src) {
    asm volatile("cp.async.cg.shared.global [%0], [%1], 16;" :: "r"(dst), "l"(src));
}
__device__ __forceinline__ void cp_commit() { asm volatile("cp.async.commit_group;"); }
template<int N> __device__ __forceinline__ void cp_wait() {
    asm volatile("cp.async.wait_group %0;" :: "n"(N));
}
__device__ __forceinline__ void ldm_x4(uint32_t& r0, uint32_t& r1, uint32_t& r2, uint32_t& r3,
                                       uint32_t addr) {
    asm volatile("ldmatrix.sync.aligned.m8n8.x4.shared.b16 {%0,%1,%2,%3}, [%4];"
                 : "=r"(r0), "=r"(r1), "=r"(r2), "=r"(r3) : "r"(addr));
}
__device__ __forceinline__ void ldm_x4_t(uint32_t& r0, uint32_t& r1, uint32_t& r2, uint32_t& r3,
                                         uint32_t addr) {
    asm volatile("ldmatrix.sync.aligned.m8n8.x4.trans.shared.b16 {%0,%1,%2,%3}, [%4];"
                 : "=r"(r0), "=r"(r1), "=r"(r2), "=r"(r3) : "r"(addr));
}
__device__ __forceinline__ void mma_f16(float* c, const uint32_t* a, const uint32_t* b) {
    asm volatile(
        "mma.sync.aligned.m16n8k16.row.col.f32.f16.f16.f32 "
        "{%0,%1,%2,%3}, {%4,%5,%6,%7}, {%8,%9}, {%0,%1,%2,%3};"
        : "+f"(c[0]), "+f"(c[1]), "+f"(c[2]), "+f"(c[3])
        : "r"(a[0]), "r"(a[1]), "r"(a[2]), "r"(a[3]), "r"(b[0]), "r"(b[1]));
}

// ---------------- fp16 GEMM: C[M,N] = A[M,K] @ op(B) + epilogue --------------
// BT=true : B stored [N,K] fp16 (use B^T) — NT, ldmatrix normal
// BT=false: B stored [K,N] fp16          — NN, ldmatrix.trans
// SPLITC  : output N split into DIMN-wide segments -> dense per-segment buffers
// EPI_EXP   : C = exp(acc * INV_SCALE); per-row sums accumulated to rowsum[]
// EPI_RSCALE: C = acc / rowsum[row]
// CTA tile 128x256, 256 threads = 8 warps of 64x64 (2x4 grid), BK=128,
// 2-stage cp.async + register-level fragment double buffering (R15 core).
enum { EPI_NONE = 0, EPI_SCALE = 1, EPI_BIAS = 2, EPI_BIAS_RESID = 3, EPI_BIAS_GELU = 4,
       EPI_EXP = 5, EPI_RSCALE = 6 };

#define NTHREADS 256
#define BK 128
#define A_BYTES (128 * BK * 2)     // 32768  (row = 256B = 16 chunks)
#define B_BYTES (256 * BK * 2)     // 65536
#define STAGE_BYTES (A_BYTES + B_BYTES)          // 98304
#define SMEM_GEMM (2 * STAGE_BYTES)              // 196608

template<bool BT>
__device__ __forceinline__ void load_tiles(const __half* __restrict__ A, int lda,
                                           const __half* __restrict__ Bg, int ldb,
                                           int m0, int n0, int kb,
                                           uint32_t as, uint32_t bs, int tid) {
    {
        const __half* src = A + (long)m0 * lda + kb * BK;
        #pragma unroll
        for (int i = 0; i < 8; i++) {
            int idx = tid + i * NTHREADS;
            int r = idx >> 4, c = idx & 15;
            cpa16(as + r * 256 + ((c ^ (r & 7)) << 4), src + (long)r * lda + c * 8);
        }
    }
    if (BT) {
        const __half* src = Bg + (long)n0 * ldb + kb * BK;
        #pragma unroll
        for (int i = 0; i < 16; i++) {
            int idx = tid + i * NTHREADS;
            int r = idx >> 4, c = idx & 15;
            cpa16(bs + r * 256 + ((c ^ (r & 7)) << 4), src + (long)r * ldb + c * 8);
        }
    } else {
        const __half* src = Bg + (long)(kb * BK) * ldb + n0;
        #pragma unroll
        for (int i = 0; i < 16; i++) {
            int idx = tid + i * NTHREADS;
            int r = idx >> 5, c = idx & 31;
            cpa16(bs + r * 512 + ((c ^ (r & 7)) << 4), src + (long)r * ldb + c * 8);
        }
    }
}

template<bool BT>
__device__ __forceinline__ void frag_load(uint32_t Ab, uint32_t Bb, int kk,
                                          int a_m, int a_kc,
                                          int b_n, int b_kc, int bn_k, int bn_nc,
                                          uint32_t af[4][4], uint32_t bf[8][2]) {
    #pragma unroll
    for (int mi = 0; mi < 4; mi++) {
        const int m = a_m + mi * 16;
        const int kc = kk * 2 + a_kc;
        ldm_x4(af[mi][0], af[mi][1], af[mi][2], af[mi][3],
               Ab + m * 256 + ((kc ^ (m & 7)) << 4));
    }
    #pragma unroll
    for (int p = 0; p < 4; p++) {
        uint32_t r0, r1, r2, r3;
        if (BT) {
            const int n = b_n + p * 16;
            const int kc = kk * 2 + b_kc;
            ldm_x4(r0, r1, r2, r3, Bb + n * 256 + ((kc ^ (n & 7)) << 4));
        } else {
            const int kr = kk * 16 + bn_k;
            const int nc = bn_nc + 2 * p;
            ldm_x4_t(r0, r1, r2, r3, Bb + kr * 512 + ((nc ^ (kr & 7)) << 4));
        }
        bf[2 * p][0] = r0; bf[2 * p][1] = r1;
        bf[2 * p + 1][0] = r2; bf[2 * p + 1][1] = r3;
    }
}

template<int EPI, bool BT, bool OUT16, bool SPLITC>
__global__ __launch_bounds__(NTHREADS, 1)
void gemm_h(const __half* __restrict__ A, int lda, long sA,
            const __half* __restrict__ Bg, int ldb, long sB,
            void* __restrict__ Cv, int ldc, long sC,
            const float* __restrict__ bias,
            const float* __restrict__ resid,
            float* __restrict__ rowsum,
            int Kdim) {
    extern __shared__ __align__(1024) char smem[];
    const uint32_t sb = smem_u32(smem);
    const int tid = threadIdx.x;
    const long bz = blockIdx.z;
    A += bz * sA; Bg += bz * sB;

    const int m0 = blockIdx.y * 128;
    const int n0 = blockIdx.x * 256;

    const int lane = tid & 31;
    const int g = lane >> 2, tg = lane & 3;
    const int wid = tid >> 5;
    const int wm0 = (wid & 1) * 64;      // 2 warp-rows of 64
    const int wn0 = (wid >> 1) * 64;     // 4 warp-cols of 64

    const int a_m = wm0 + (lane & 15);
    const int a_kc = lane >> 4;
    const int b_n = wn0 + (lane & 7) + ((lane >> 4) << 3);
    const int b_kc = (lane >> 3) & 1;
    const int bn_k = (lane & 7) + (lane & 8);
    const int bn_nc = (wn0 >> 3) + (lane >> 4);

    float acc[4][8][4];
    #pragma unroll
    for (int i = 0; i < 4; i++)
        #pragma unroll
        for (int j = 0; j < 8; j++)
            #pragma unroll
            for (int r = 0; r < 4; r++) acc[i][j][r] = 0.0f;

    const int nk = Kdim / BK;
    load_tiles<BT>(A, lda, Bg, ldb, m0, n0, 0, sb, sb + A_BYTES, tid);
    cp_commit();
    load_tiles<BT>(A, lda, Bg, ldb, m0, n0, 1, sb + STAGE_BYTES, sb + STAGE_BYTES + A_BYTES, tid);
    cp_commit();

    for (int kb = 0; kb < nk; ++kb) {
        if (kb + 1 < nk) cp_wait<1>(); else cp_wait<0>();
        __syncthreads();

        const uint32_t Ab = sb + (kb & 1) * STAGE_BYTES;
        const uint32_t Bb = Ab + A_BYTES;

        uint32_t af[2][4][4];
        uint32_t bf[2][8][2];
        frag_load<BT>(Ab, Bb, 0, a_m, a_kc, b_n, b_kc, bn_k, bn_nc, af[0], bf[0]);

        #pragma unroll
        for (int kk = 0; kk < 8; kk++) {
            const int cur = kk & 1;
            if (kk < 7)
                frag_load<BT>(Ab, Bb, kk + 1, a_m, a_kc, b_n, b_kc, bn_k, bn_nc,
                              af[cur ^ 1], bf[cur ^ 1]);
            #pragma unroll
            for (int mi = 0; mi < 4; mi++)
                #pragma unroll
                for (int nj = 0; nj < 8; nj++)
                    mma_f16(acc[mi][nj], af[cur][mi], bf[cur][nj]);
        }
        __syncthreads();

        if (kb + 2 < nk) {
            const uint32_t st = sb + (kb & 1) * STAGE_BYTES;
            load_tiles<BT>(A, lda, Bg, ldb, m0, n0, kb + 2, st, st + A_BYTES, tid);
            cp_commit();
        }
    }

    // epilogue
    float* srow = (float*)smem;          // reused (all warps past final sync)
    if (EPI == EPI_EXP) {
        if (tid < 128) srow[tid] = 0.0f;
        __syncthreads();
    }
    const int  seg     = SPLITC ? (n0 / DIMN) : 0;
    const long seg_off = SPLITC ? (long)seg * ((long)NTOK * DIMN) - (long)seg * DIMN : 0;
    #pragma unroll
    for (int mi = 0; mi < 4; mi++) {
        #pragma unroll
        for (int r2 = 0; r2 < 2; r2++) {
            const int row = m0 + wm0 + mi * 16 + g + r2 * 8;
            float rinv = 0.0f, rsum = 0.0f;
            if (EPI == EPI_RSCALE) rinv = 1.0f / rowsum[bz * NS + row];
            #pragma unroll
            for (int nj = 0; nj < 8; nj++) {
                const int col = n0 + wn0 + nj * 8 + 2 * tg;
                float v0 = acc[mi][nj][r2 * 2 + 0];
                float v1 = acc[mi][nj][r2 * 2 + 1];
                long off;
                if (SPLITC) {
                    off = seg_off + (long)row * DIMN + col;
                } else {
                    off = (long)row * ldc + col + bz * sC;
                }
                if (EPI == EPI_SCALE) { v0 *= INV_SCALE_F; v1 *= INV_SCALE_F; }
                if (EPI == EPI_EXP) {
                    v0 = __expf(v0 * INV_SCALE_F);
                    v1 = __expf(v1 * INV_SCALE_F);
                    rsum += v0 + v1;
                }
                if (EPI == EPI_RSCALE) { v0 *= rinv; v1 *= rinv; }
                if (EPI == EPI_BIAS || EPI == EPI_BIAS_RESID || EPI == EPI_BIAS_GELU) {
                    v0 += bias[col]; v1 += bias[col + 1];
                }
                if (EPI == EPI_BIAS_RESID) {
                    float2 rr = *(const float2*)(resid + off);
                    v0 += rr.x; v1 += rr.y;
                }
                if (EPI == EPI_BIAS_GELU) { v0 = geluf(v0); v1 = geluf(v1); }
                if (OUT16) {
                    *(__half2*)((__half*)Cv + off) = __floats2half2_rn(v0, v1);
                } else {
                    float2 o; o.x = v0; o.y = v1;
                    *(float2*)((float*)Cv + off) = o;
                }
            }
            if (EPI == EPI_EXP) {
                // reduce across the 4 tg lanes sharing this row
                rsum += __shfl_xor_sync(0xffffffffu, rsum, 1);
                rsum += __shfl_xor_sync(0xffffffffu, rsum, 2);
                if (tg == 0) atomicAdd(&srow[row - m0], rsum);
            }
        }
    }
    if (EPI == EPI_EXP) {
        __syncthreads();
        if (tid < 128) atomicAdd(&rowsum[bz * NS + m0 + tid], srow[tid]);
    }
}

// ---------------- fp32 -> fp16 conversion (x) --------------------------------
__global__ __launch_bounds__(256)
void cvt_kernel(const float* __restrict__ src, __half* __restrict__ dst) {
    const long i = ((long)blockIdx.x * 256 + threadIdx.x) * 4;
    float4 v = *(const float4*)(src + i);
    uint2 o;
    __half2 h0 = __floats2half2_rn(v.x, v.y);
    __half2 h1 = __floats2half2_rn(v.z, v.w);
    o.x = *(uint32_t*)&h0; o.y = *(uint32_t*)&h1;
    *(uint2*)(dst + i) = o;
}

// ---------------- rowsum zero -------------------------------------------------
__global__ __launch_bounds__(256)
void zero_rs(float* __restrict__ rs) {
    rs[blockIdx.x * 256 + threadIdx.x] = 0.0f;
}

// ---------------- weights (Wq|Wk|Wv concat, Wp, W1, W2) + bias concat --------
#define WSZ (DIMN * DIMN)
#define W1SZ (HIDN * DIMN)
#define WTOTAL (4L * WSZ + 2L * W1SZ)
#define CVT_UNITS (WTOTAL / 4 + QKVN / 4)
#define CVTW_GRID ((CVT_UNITS + 255) / 256)
__global__ __launch_bounds__(256)
void cvt_weights(const float* __restrict__ Wq, const float* __restrict__ Wk,
                 const float* __restrict__ Wv, const float* __restrict__ Wp,
                 const float* __restrict__ W1, const float* __restrict__ W2,
                 const float* __restrict__ bq, const float* __restrict__ bk,
                 const float* __restrict__ bv,
                 __half* __restrict__ dWqkv, __half* __restrict__ dWp,
                 __half* __restrict__ dW1, __half* __restrict__ dW2,
                 float* __restrict__ dbqkv) {
    const long u = (long)blockIdx.x * 256 + threadIdx.x;
    if (u >= CVT_UNITS) return;
    long i = u * 4;
    if (i < WTOTAL) {
        const float* src;
        __half* dst;
        if (i < WSZ)              { src = Wq; dst = dWqkv; }
        else if (i < 2L * WSZ)    { src = Wk; dst = dWqkv + WSZ; i -= WSZ; }
        else if (i < 3L * WSZ)    { src = Wv; dst = dWqkv + 2L * WSZ; i -= 2L * WSZ; }
        else if (i < 4L * WSZ)    { src = Wp; dst = dWp; i -= 3L * WSZ; }
        else if (i < 4L * WSZ + W1SZ) { src = W1; dst = dW1; i -= 4L * WSZ; }
        else                      { src = W2; dst = dW2; i -= 4L * WSZ + W1SZ; }
        float4 v = *(const float4*)(src + i);
        uint2 o;
        __half2 h0 = __floats2half2_rn(v.x, v.y);
        __half2 h1 = __floats2half2_rn(v.z, v.w);
        o.x = *(uint32_t*)&h0; o.y = *(uint32_t*)&h1;
        *(uint2*)(dst + i) = o;
    } else {
        long j = i - WTOTAL;
        const float* src = (j < DIMN) ? (bq + j)
                         : (j < 2 * DIMN) ? (bk + (j - DIMN))
                                          : (bv + (j - 2 * DIMN));
        *(float4*)(dbqkv + j) = *(const float4*)src;
    }
}

// ---------------- LayerNorm over rows of 768 (one warp per row) --------------
__global__ __launch_bounds__(128)
void ln_kernel(const float* __restrict__ in, const float* __restrict__ gamma,
               const float* __restrict__ beta, float* __restrict__ out,
               __half* __restrict__ out16) {
    const int wid = threadIdx.x >> 5, lane = threadIdx.x & 31;
    const long row = (long)blockIdx.x * 4 + wid;
    const float4* p = (const float4*)(in + row * DIMN);

    float4 v[6];
    float s = 0.0f, sq = 0.0f;
    #pragma unroll
    for (int j = 0; j < 6; j++) {
        v[j] = p[lane + 32 * j];
        s  += (v[j].x + v[j].y) + (v[j].z + v[j].w);
        sq += (v[j].x * v[j].x + v[j].y * v[j].y) + (v[j].z * v[j].z + v[j].w * v[j].w);
    }
    #pragma unroll
    for (int o = 16; o > 0; o >>= 1) {
        s  += __shfl_xor_sync(0xffffffffu, s, o);
        sq += __shfl_xor_sync(0xffffffffu, sq, o);
    }
    const float mean = s * (1.0f / DIMN);
    const float var  = sq * (1.0f / DIMN) - mean * mean;
    const float ri   = rsqrtf(var + 1e-12f);

    const float4* gp = (const float4*)gamma;
    const float4* bp = (const float4*)beta;
    float4* o = (float4*)(out + row * DIMN);
    #pragma unroll
    for (int j = 0; j < 6; j++) {
        float4 g4 = gp[lane + 32 * j], b4 = bp[lane + 32 * j], r;
        r.x = (v[j].x - mean) * ri * g4.x + b4.x;
        r.y = (v[j].y - mean) * ri * g4.y + b4.y;
        r.z = (v[j].z - mean) * ri * g4.z + b4.z;
        r.w = (v[j].w - mean) * ri * g4.w + b4.w;
        o[lane + 32 * j] = r;
        if (out16) {
            __half2 h0 = __floats2half2_rn(r.x, r.y);
            __half2 h1 = __floats2half2_rn(r.z, r.w);
            uint2 w; w.x = *(uint32_t*)&h0; w.y = *(uint32_t*)&h1;
            *(uint2*)(out16 + row * DIMN + (lane + 32 * j) * 4) = w;
        }
    }
}

// ---------------- launch ------------------------------------------------------
extern "C" void kernel_launch(void* const* d_in, const int* in_sizes, int n_in,
                              void* d_out, int out_size) {
    const float* x   = (const float*)d_in[0];
    const float* Wq  = (const float*)d_in[1];
    const float* bq  = (const float*)d_in[2];
    const float* Wk  = (const float*)d_in[3];
    const float* bk  = (const float*)d_in[4];
    const float* Wv  = (const float*)d_in[5];
    const float* bv  = (const float*)d_in[6];
    const float* Wp  = (const float*)d_in[7];
    const float* bp  = (const float*)d_in[8];
    const float* g1  = (const float*)d_in[9];
    const float* be1 = (const float*)d_in[10];
    const float* W1  = (const float*)d_in[11];
    const float* b1  = (const float*)d_in[12];
    const float* W2  = (const float*)d_in[13];
    const float* b2  = (const float*)d_in[14];
    const float* g2  = (const float*)d_in[15];
    const float* be2 = (const float*)d_in[16];
    float* out = (float*)d_out;

    __half *xh, *QKV3, *alphah, *attnh, *hh, *mlph;
    __half *Wqkvh, *Wph, *W1h, *W2h;
    float *t1, *h32, *t2, *bqkv, *rowsum;
    cudaGetSymbolAddress((void**)&xh, g_xh);
    cudaGetSymbolAddress((void**)&QKV3, g_QKV3);
    cudaGetSymbolAddress((void**)&alphah, g_alphah);
    cudaGetSymbolAddress((void**)&rowsum, g_rowsum);
    cudaGetSymbolAddress((void**)&attnh, g_attnh);
    cudaGetSymbolAddress((void**)&t1, g_t1);
    cudaGetSymbolAddress((void**)&h32, g_h32);
    cudaGetSymbolAddress((void**)&hh, g_hh);
    cudaGetSymbolAddress((void**)&mlph, g_mlph);
    cudaGetSymbolAddress((void**)&t2, g_t2);
    cudaGetSymbolAddress((void**)&Wqkvh, g_Wqkvh);
    cudaGetSymbolAddress((void**)&bqkv, g_bqkv);
    cudaGetSymbolAddress((void**)&Wph, g_Wph);
    cudaGetSymbolAddress((void**)&W1h, g_W1h);
    cudaGetSymbolAddress((void**)&W2h, g_W2h);

    __half* Qh = QKV3;
    __half* Kh = QKV3 + (long)NTOK * DIMN;
    __half* Vh = QKV3 + 2L * NTOK * DIMN;

    cudaFuncSetAttribute(gemm_h<EPI_BIAS, true, true, true>,          cudaFuncAttributeMaxDynamicSharedMemorySize, SMEM_GEMM);
    cudaFuncSetAttribute(gemm_h<EPI_EXP, true, true, false>,          cudaFuncAttributeMaxDynamicSharedMemorySize, SMEM_GEMM);
    cudaFuncSetAttribute(gemm_h<EPI_RSCALE, false, true, false>,      cudaFuncAttributeMaxDynamicSharedMemorySize, SMEM_GEMM);
    cudaFuncSetAttribute(gemm_h<EPI_BIAS_RESID, true, false, false>,  cudaFuncAttributeMaxDynamicSharedMemorySize, SMEM_GEMM);
    cudaFuncSetAttribute(gemm_h<EPI_BIAS_GELU, true, true, false>,    cudaFuncAttributeMaxDynamicSharedMemorySize, SMEM_GEMM);

    // #1: x fp32->fp16 ; #2: weights (QKV concat) + bias concat ; #3: zero rowsum
    cvt_kernel<<<(long)NTOK * DIMN / 1024, 256>>>(x, xh);
    cvt_weights<<<CVTW_GRID, 256>>>(Wq, Wk, Wv, Wp, W1, W2, bq, bk, bv,
                                    Wqkvh, Wph, W1h, W2h, bqkv);
    zero_rs<<<NTOK / 256, 256>>>(rowsum);

    const dim3 blk(NTHREADS);
    const long sQK = (long)NS * DIMN;
    const long sAl = (long)NS * NS;

    // #4: fused QKV projection (one launch, SPLITC dense outputs)
    gemm_h<EPI_BIAS, true, true, true><<<dim3(9, 128, 1), blk, SMEM_GEMM>>>(
        xh, DIMN, 0, Wqkvh, DIMN, 0, QKV3, DIMN, 0, bqkv, nullptr, nullptr, DIMN);

    // #5: alpha = exp(Q @ K^T / sqrt(D)) + rowsum accumulation (fused softmax pt.1)
    gemm_h<EPI_EXP, true, true, false><<<dim3(8, 16, NB), blk, SMEM_GEMM>>>(
        Qh, DIMN, sQK, Kh, DIMN, sQK, alphah, NS, sAl, nullptr, nullptr, rowsum, DIMN);

    // #6 (ncu capture): attn = (alpha @ V) / rowsum (fused softmax pt.2)
    gemm_h<EPI_RSCALE, false, true, false><<<dim3(3, 16, NB), blk, SMEM_GEMM>>>(
        alphah, NS, sAl, Vh, DIMN, sQK, attnh, DIMN, sQK, nullptr, nullptr, rowsum, NS);

    // proj + residual: t1 = attn @ Wp^T + bp + x  (fp32 out)
    gemm_h<EPI_BIAS_RESID, true, false, false><<<dim3(3, 128, 1), blk, SMEM_GEMM>>>(
        attnh, DIMN, 0, Wph, DIMN, 0, t1, DIMN, 0, bp, x, nullptr, DIMN);

    // h = LN(t1)  (fp32 + fp16)
    ln_kernel<<<NTOK / 4, 128>>>(t1, g1, be1, h32, hh);

    // mlp = gelu(h @ W1^T + b1)  (fp16 out)
    gemm_h<EPI_BIAS_GELU, true, true, false><<<dim3(6, 128, 1), blk, SMEM_GEMM>>>(
        hh, DIMN, 0, W1h, DIMN, 0, mlph, HIDN, 0, b1, nullptr, nullptr, DIMN);

    // t2 = mlp @ W2^T + b2 + h  (fp32 out)
    gemm_h<EPI_BIAS_RESID, true, false, false><<<dim3(3, 128, 1), blk, SMEM_GEMM>>>(
        mlph, HIDN, 0, W2h, HIDN, 0, t2, DIMN, 0, b2, h32, nullptr, HIDN);

    // out = LN(t2)
    ln_kernel<<<NTOK / 4, 128>>>(t2, g2, be2, out, nullptr);
}